// round 14
// baseline (speedup 1.0000x reference)
#include <cuda_runtime.h>
#include <cuda_fp16.h>
#include <math.h>

#define HW 9216
#define WN 96
#define NB 2
#define NF 4
#define NH 8
#define CC 128

typedef unsigned long long ull;

// ---------------- scratch (device globals; no allocation allowed) ----------------
__device__ float   g_qperm[2359296];   // [B, HEADS, HW, 16]
__device__ float   g_vnear[2359296];   // [B, HEADS, HW, 16]  (fp32 nearest frame)
__device__ __half2 g_vh  [4718592];    // fp16 all frames: [(b*4+n)*8+head][hw][8 half2]
__device__ float   g_dwtmp[2359296];   // [B, C, HW]
__device__ float   g_net  [2359296];   // [B*HEADS*HW, 16]
__device__ float   g_off  [1179648];   // [B*HEADS*HW, P, 2]
__device__ float   g_attn [589824];    // [B*HEADS*HW, P]
__device__ float   g_agg  [2359296];   // [B, C, HW]
__device__ float   g_tmp2 [2359296];   // [B, C, HW]
__device__ float   g_ent  [147456];    // [B*HEADS*HW]
__device__ float   g_tbias[64];        // [B, HEADS, N]
__device__ int     g_nearest[2];

// ---------------- helpers ----------------
__device__ __forceinline__ float geluf(float v){
    return 0.5f * v * (1.0f + erff(v * 0.70710678118654752f));
}
__device__ __forceinline__ float sigmoidf_(float v){
    return 1.0f / (1.0f + expf(-v));
}
__device__ __forceinline__ ull pk2(float x, float y){
    ull r;
    asm("mov.b64 %0, {%1,%2};" : "=l"(r) : "f"(x), "f"(y));
    return r;
}
__device__ __forceinline__ void upk2(ull v, float& x, float& y){
    asm("mov.b64 {%0,%1}, %2;" : "=f"(x), "=f"(y) : "l"(v));
}
__device__ __forceinline__ ull ffma2(ull a, ull b, ull c){
    ull d;
    asm("fma.rn.f32x2 %0, %1, %2, %3;" : "=l"(d) : "l"(a), "l"(b), "l"(c));
    return d;
}
__device__ __forceinline__ unsigned smem_u32(const void* p){
    return (unsigned)__cvta_generic_to_shared(p);
}

// ---------------- conv1x1 as tiled GEMM (fp32 FFMA2, 8x8 microtile) ----------------
// MODE: 1 = NCHW out + gelu, 2 = NCHW out * sigmoid(gate), 3 = head-permuted out (no act)
static constexpr int CONV_SMEM_BYTES = (128*132 + 64*132) * 4;  // 101376 B

// Shared GEMM core: 128 threads, tile 64px x 128o, 8x8 per thread.
// sIn: [c:128][px:64], sW: [c:128][o pitch 132]. Result staged into sStage[px][132].
template<int MODE>
__device__ __forceinline__ void conv_core(
    const float* sW, const float* sIn, float* sStage,
    const float* __restrict__ bias, const float* __restrict__ gate, int tid)
{
    const int px8 = (tid & 7) * 8;
    const int o8  = (tid >> 3) * 8;
    ull acc[8][4];
    #pragma unroll
    for (int i = 0; i < 8; i++)
        #pragma unroll
        for (int j = 0; j < 4; j++) acc[i][j] = 0ull;

    #pragma unroll 4
    for (int c = 0; c < 128; c++){
        float4 a0 = *(const float4*)(sIn + c*64 + px8);
        float4 a1 = *(const float4*)(sIn + c*64 + px8 + 4);
        ulonglong2 w0 = *(const ulonglong2*)(sW + c*132 + o8);
        ulonglong2 w1 = *(const ulonglong2*)(sW + c*132 + o8 + 4);
        ull ap[8];
        ap[0] = pk2(a0.x, a0.x); ap[1] = pk2(a0.y, a0.y);
        ap[2] = pk2(a0.z, a0.z); ap[3] = pk2(a0.w, a0.w);
        ap[4] = pk2(a1.x, a1.x); ap[5] = pk2(a1.y, a1.y);
        ap[6] = pk2(a1.z, a1.z); ap[7] = pk2(a1.w, a1.w);
        #pragma unroll
        for (int i = 0; i < 8; i++){
            acc[i][0] = ffma2(ap[i], w0.x, acc[i][0]);
            acc[i][1] = ffma2(ap[i], w0.y, acc[i][1]);
            acc[i][2] = ffma2(ap[i], w1.x, acc[i][2]);
            acc[i][3] = ffma2(ap[i], w1.y, acc[i][3]);
        }
    }
    __syncthreads();

    float bl[8];
    #pragma unroll
    for (int j = 0; j < 8; j++) bl[j] = bias[o8 + j];
    float gl[8];
    if (MODE == 2){
        #pragma unroll
        for (int j = 0; j < 8; j++) gl[j] = sigmoidf_(gate[o8 + j]);
    }

    #pragma unroll
    for (int i = 0; i < 8; i++){
        #pragma unroll
        for (int j2 = 0; j2 < 4; j2++){
            float v0, v1;
            upk2(acc[i][j2], v0, v1);
            int j = j2 * 2;
            v0 += bl[j]; v1 += bl[j+1];
            if (MODE == 1){ v0 = geluf(v0); v1 = geluf(v1); }
            if (MODE == 2){ v0 *= gl[j]; v1 *= gl[j+1]; }
            sStage[(px8+i)*132 + o8 + j    ] = v0;
            sStage[(px8+i)*132 + o8 + j + 1] = v1;
        }
    }
    __syncthreads();
}

__device__ __forceinline__ void conv_load(
    float* sW, float* sIn, const float* __restrict__ wgt,
    const float* __restrict__ inp, int tid)
{
    #pragma unroll 8
    for (int i = tid; i < 16384; i += 128){
        int o = i >> 7, c = i & 127;
        sW[c*132 + o] = wgt[i];
    }
    #pragma unroll 8
    for (int i = tid; i < 8192; i += 128){
        int c = i >> 6, p = i & 63;
        sIn[c*64 + p] = inp[(size_t)c*HW + p];
    }
    __syncthreads();
}

template<int MODE>
__global__ void __launch_bounds__(128, 2) conv1x1_k(
    const float* __restrict__ in, const float* __restrict__ wgt,
    const float* __restrict__ bias, float* __restrict__ out,
    const float* __restrict__ gate)
{
    extern __shared__ float sm[];
    float* sW = sm;               // [c][o] pitch 132
    float* sB = sm + 128*132;     // in tile [c][64] then stage [px][o] pitch 132
    const int tid = threadIdx.x;
    const int img = blockIdx.y;
    const int px0 = blockIdx.x * 64;
    const float* inp = in + (size_t)img * (128*HW) + px0;

    conv_load(sW, sB, wgt, inp, tid);
    conv_core<MODE>(sW, sB, sB, bias, gate, tid);

    if (MODE >= 3){
        #pragma unroll 8
        for (int i = tid; i < 8192; i += 128){
            int head = i >> 10, local = i & 1023;
            int px = local >> 4;
            out[(((size_t)img*8 + head)*HW + px0)*16 + local] = sB[px*132 + head*16 + (local & 15)];
        }
    } else {
        #pragma unroll 8
        for (int i = tid; i < 8192; i += 128){
            int o = i >> 6, p = i & 63;
            out[(size_t)img*(128*HW) + (size_t)o*HW + px0 + p] = sB[p*132 + o];
        }
    }
}

// batched q-conv (y<2) + vnear-conv (y>=2, nearest frame), both head-permuted
__global__ void __launch_bounds__(128, 2) conv_qv_k(
    const float* __restrict__ q_in, const float* __restrict__ qw,
    const float* __restrict__ qb, float* __restrict__ q_out,
    const float* __restrict__ v_in, const float* __restrict__ vw,
    const float* __restrict__ vb, float* __restrict__ v_out)
{
    extern __shared__ float sm[];
    float* sW = sm;
    float* sB = sm + 128*132;
    const int tid = threadIdx.x;
    const bool isv = blockIdx.y >= 2;
    const int img = blockIdx.y & 1;
    const int px0 = blockIdx.x * 64;

    const float* inp;
    const float* wgt;
    const float* bias;
    float* out;
    if (isv){
        inp = v_in + (size_t)(img*4 + g_nearest[img]) * (128*HW) + px0;
        wgt = vw; bias = vb; out = v_out;
    } else {
        inp = q_in + (size_t)img * (128*HW) + px0;
        wgt = qw; bias = qb; out = q_out;
    }

    conv_load(sW, sB, wgt, inp, tid);
    conv_core<3>(sW, sB, sB, bias, nullptr, tid);

    #pragma unroll 8
    for (int i = tid; i < 8192; i += 128){
        int head = i >> 10, local = i & 1023;
        int px = local >> 4;
        out[(((size_t)img*8 + head)*HW + px0)*16 + local] = sB[px*132 + head*16 + (local & 15)];
    }
}

// ---------------- fp16 tensor-core conv1x1: all-frames v -> g_vh only ----------------
static constexpr int CONVH_SMEM_BYTES = 2 * 128 * 136 * 2;  // 69632 B

__global__ void __launch_bounds__(256, 2) convh_k(
    const float* __restrict__ in, const float* __restrict__ wgt,
    const float* __restrict__ bias, __half2* __restrict__ out)
{
    extern __shared__ __half sh[];
    __half* sA = sh;              // [c][px] pitch 136
    __half* sB = sh + 128*136;    // [o][c] pitch 136
    const int tid = threadIdx.x;
    const int img = blockIdx.y;
    const int px0 = blockIdx.x * 128;
    const float* inp = in + (size_t)img * (128*HW) + px0;

    #pragma unroll 8
    for (int i = tid; i < 4096; i += 256){
        int c = i >> 5, p4 = (i & 31) * 4;
        float4 v = *(const float4*)(inp + (size_t)c*HW + p4);
        __half2* d = (__half2*)(sA + c*136 + p4);
        d[0] = __floats2half2_rn(v.x, v.y);
        d[1] = __floats2half2_rn(v.z, v.w);
    }
    #pragma unroll 8
    for (int i = tid; i < 4096; i += 256){
        int o = i >> 5, c4 = (i & 31) * 4;
        float4 v = *(const float4*)(wgt + o*128 + c4);
        __half2* d = (__half2*)(sB + o*136 + c4);
        d[0] = __floats2half2_rn(v.x, v.y);
        d[1] = __floats2half2_rn(v.z, v.w);
    }
    __syncthreads();

    const int wid = tid >> 5, lane = tid & 31;
    const int px_w = (wid & 1) * 64;
    const int o_w  = (wid >> 1) * 32;
    const int lr = lane & 7, lg = lane >> 3;

    float acc[4][4][4];
    #pragma unroll
    for (int m = 0; m < 4; m++)
        #pragma unroll
        for (int n = 0; n < 4; n++)
            #pragma unroll
            for (int r = 0; r < 4; r++) acc[m][n][r] = 0.0f;

    #pragma unroll
    for (int k0 = 0; k0 < 128; k0 += 16){
        unsigned a[4][4], b[4][2];
        #pragma unroll
        for (int mt = 0; mt < 4; mt++){
            int px = px_w + mt*16 + ((lg & 1) ? 8 : 0);
            int kk = k0 + lr + ((lg & 2) ? 8 : 0);
            unsigned addr = smem_u32(sA + kk*136 + px);
            asm volatile("ldmatrix.sync.aligned.m8n8.x4.trans.shared.b16 {%0,%1,%2,%3}, [%4];"
                : "=r"(a[mt][0]), "=r"(a[mt][1]), "=r"(a[mt][2]), "=r"(a[mt][3]) : "r"(addr));
        }
        #pragma unroll
        for (int nt2 = 0; nt2 < 2; nt2++){
            int oo = o_w + nt2*16 + lr + ((lg & 2) ? 8 : 0);
            int kk = k0 + ((lg & 1) ? 8 : 0);
            unsigned addr = smem_u32(sB + oo*136 + kk);
            unsigned r0, r1, r2, r3;
            asm volatile("ldmatrix.sync.aligned.m8n8.x4.shared.b16 {%0,%1,%2,%3}, [%4];"
                : "=r"(r0), "=r"(r1), "=r"(r2), "=r"(r3) : "r"(addr));
            b[2*nt2][0] = r0;   b[2*nt2][1] = r1;
            b[2*nt2+1][0] = r2; b[2*nt2+1][1] = r3;
        }
        #pragma unroll
        for (int mt = 0; mt < 4; mt++)
            #pragma unroll
            for (int nt = 0; nt < 4; nt++){
                asm volatile(
                    "mma.sync.aligned.m16n8k16.row.col.f32.f16.f16.f32 "
                    "{%0,%1,%2,%3}, {%4,%5,%6,%7}, {%8,%9}, {%0,%1,%2,%3};"
                    : "+f"(acc[mt][nt][0]), "+f"(acc[mt][nt][1]),
                      "+f"(acc[mt][nt][2]), "+f"(acc[mt][nt][3])
                    : "r"(a[mt][0]), "r"(a[mt][1]), "r"(a[mt][2]), "r"(a[mt][3]),
                      "r"(b[nt][0]), "r"(b[nt][1]));
            }
    }

    float bl[4][2];
    #pragma unroll
    for (int nt = 0; nt < 4; nt++){
        int o = o_w + nt*8 + (lane & 3)*2;
        bl[nt][0] = bias[o]; bl[nt][1] = bias[o+1];
    }
    #pragma unroll
    for (int mt = 0; mt < 4; mt++){
        int pxr = px0 + px_w + mt*16 + (lane >> 2);
        #pragma unroll
        for (int nt = 0; nt < 4; nt++){
            int o = o_w + nt*8 + (lane & 3)*2;
            int head = o >> 4, pr = (o & 15) >> 1;
            __half2 h0 = __floats2half2_rn(acc[mt][nt][0] + bl[nt][0], acc[mt][nt][1] + bl[nt][1]);
            __half2 h1 = __floats2half2_rn(acc[mt][nt][2] + bl[nt][0], acc[mt][nt][3] + bl[nt][1]);
            size_t base = ((size_t)(img*8 + head)*HW);
            out[(base + pxr    )*8 + pr] = h0;
            out[(base + pxr + 8)*8 + pr] = h1;
        }
    }
}

// ---------------- depthwise 7x7 + gelu (smem-tiled) ----------------
__global__ void __launch_bounds__(384) dwconv_k(
    const float* __restrict__ q, const float* __restrict__ dww,
    const float* __restrict__ dwb, float* __restrict__ out)
{
    __shared__ float swm[49];
    __shared__ float tile[22*104];
    const int plane = blockIdx.y;
    const int c = plane & 127;
    const int ty0 = blockIdx.x * 16;
    const int tid = threadIdx.y * 96 + threadIdx.x;
    if (tid < 49) swm[tid] = dww[c*49 + tid];
    const float* qp = q + (size_t)plane * HW;
    for (int i = tid; i < 22*104; i += 384){
        int r = i / 104, xc = i - r*104;
        int gy = ty0 - 3 + r, gx = xc - 3;
        float v = 0.0f;
        if ((unsigned)gy < 96u && (unsigned)gx < 96u) v = qp[gy*WN + gx];
        tile[i] = v;
    }
    __syncthreads();

    float w[49];
    #pragma unroll
    for (int i = 0; i < 49; i++) w[i] = swm[i];

    const int tx = threadIdx.x;
    const int ly0 = threadIdx.y * 4;
    float acc[4];
    float bb = dwb[c];
    #pragma unroll
    for (int o = 0; o < 4; o++) acc[o] = bb;

    #pragma unroll
    for (int r = 0; r < 10; r++){
        float in7[7];
        #pragma unroll
        for (int j = 0; j < 7; j++) in7[j] = tile[(ly0 + r)*104 + tx + j];
        #pragma unroll
        for (int o = 0; o < 4; o++){
            int ky = r - o;
            if (ky >= 0 && ky <= 6){
                #pragma unroll
                for (int kx = 0; kx < 7; kx++)
                    acc[o] += in7[kx] * w[ky*7 + kx];
            }
        }
    }
    #pragma unroll
    for (int o = 0; o < 4; o++){
        int gy = ty0 + ly0 + o;
        out[(size_t)plane*HW + gy*WN + tx] = geluf(acc[o]);
    }
}

// ---------------- prep: nearest idx + time bias ----------------
__global__ void prep_k(const float* __restrict__ rel_time, const float* __restrict__ time_enc,
                       const float* __restrict__ tw, const float* __restrict__ tb)
{
    int t = threadIdx.x;
    if (t < 2){
        int best = 0; float bv = fabsf(rel_time[t*4]);
        for (int n = 1; n < 4; n++){
            float v = fabsf(rel_time[t*4 + n]);
            if (v < bv){ bv = v; best = n; }
        }
        g_nearest[t] = best;
    }
    if (t < 64){
        int b = t >> 5, rem = t & 31, head = rem >> 2, n = rem & 3;
        float s = tb[head];
        for (int tc = 0; tc < 64; tc++)
            s += time_enc[(b*4 + n)*64 + tc] * tw[head*64 + tc];
        g_tbias[(b*8 + head)*4 + n] = s;
    }
}

// ---------------- correlation argmax -> initial offsets ----------------
__global__ void __launch_bounds__(256) corr_k()
{
    int row = blockIdx.x * 256 + threadIdx.x;
    int b = row / (8*HW);
    int rem = row - b * (8*HW);
    int head = rem / HW;
    int px = rem - head * HW;
    int y = px / WN, x = px - y * WN;
    const float4* qv = (const float4*)(g_qperm + (size_t)row * 16);
    float4 q0 = qv[0], q1 = qv[1], q2 = qv[2], q3 = qv[3];
    const float* vb = g_vnear + ((size_t)(b*8 + head) * HW) * 16;
    const int sdx[5] = {0, -1, 1, 0, 0};
    const int sdy[5] = {0,  0, 0,-1, 1};
    int best = 0; float bs = 0.0f;
    #pragma unroll
    for (int s = 0; s < 5; s++){
        int yy = y - sdy[s], xx = x - sdx[s];
        float sc = 0.0f;
        if ((unsigned)yy < 96u && (unsigned)xx < 96u){
            const float4* vv = (const float4*)(vb + (yy*WN + xx)*16);
            float4 v0 = vv[0], v1 = vv[1], v2 = vv[2], v3 = vv[3];
            sc = q0.x*v0.x + q0.y*v0.y + q0.z*v0.z + q0.w*v0.w
               + q1.x*v1.x + q1.y*v1.y + q1.z*v1.z + q1.w*v1.w
               + q2.x*v2.x + q2.y*v2.y + q2.z*v2.z + q2.w*v2.w
               + q3.x*v3.x + q3.y*v3.y + q3.z*v3.z + q3.w*v3.w;
        }
        if (s == 0){ bs = sc; }
        else if (sc > bs){ bs = sc; best = s; }
    }
    float offx = sdy[best] * (2.0f/96.0f);
    float offy = sdx[best] * (2.0f/96.0f);
    float* op = g_off + (size_t)row * 8;
    #pragma unroll
    for (int p = 0; p < 4; p++){ op[2*p] = offx; op[2*p+1] = offy; }
    *(float4*)(g_attn + (size_t)row * 4) = make_float4(0.f, 0.f, 0.f, 0.f);
}

// ---------------- GRU iteration (packed FFMA2) ----------------
__global__ void __launch_bounds__(128, 3) gru_k(
    const float* __restrict__ wih, const float* __restrict__ whh,
    const float* __restrict__ bih, const float* __restrict__ bhh,
    const float* __restrict__ offw, const float* __restrict__ offb,
    const float* __restrict__ aw, const float* __restrict__ ab)
{
    __shared__ __align__(16) float s_wiRZ[576];
    __shared__ __align__(16) float s_whRZ[512];
    __shared__ __align__(16) float s_wiNN[288];
    __shared__ __align__(16) float s_whNN[256];
    __shared__ __align__(16) float s_offw2[128];
    __shared__ __align__(16) float s_aw2[64];
    __shared__ __align__(16) float s_brz[32];
    __shared__ __align__(16) float s_bin[16];
    __shared__ __align__(16) float s_bhn[16];
    __shared__ __align__(16) float s_offb2[8];
    __shared__ __align__(16) float s_ab2[8];
    const int tid = threadIdx.x;
    for (int i = tid; i < 288; i += 128){ int g = i/18, k = i - g*18;
        s_wiRZ[g*36 + 2*k]   = wih[g*18 + k];
        s_wiRZ[g*36 + 2*k+1] = wih[(g+16)*18 + k]; }
    for (int i = tid; i < 256; i += 128){ int g = i >> 4, k = i & 15;
        s_whRZ[g*32 + 2*k]   = whh[g*16 + k];
        s_whRZ[g*32 + 2*k+1] = whh[(g+16)*16 + k]; }
    for (int i = tid; i < 144; i += 128){ int g2 = i/18, k = i - g2*18;
        s_wiNN[g2*36 + 2*k]   = wih[(32+2*g2)*18 + k];
        s_wiNN[g2*36 + 2*k+1] = wih[(33+2*g2)*18 + k]; }
    if (tid < 128){ int g2 = tid >> 4, k = tid & 15;
        s_whNN[g2*32 + 2*k]   = whh[(32+2*g2)*16 + k];
        s_whNN[g2*32 + 2*k+1] = whh[(33+2*g2)*16 + k]; }
    if (tid < 64){ int j2 = tid >> 4, k = tid & 15;
        s_offw2[j2*32 + 2*k]   = offw[(2*j2)*16 + k];
        s_offw2[j2*32 + 2*k+1] = offw[(2*j2+1)*16 + k]; }
    if (tid < 32){ int j2 = tid >> 4, k = tid & 15;
        s_aw2[j2*32 + 2*k]   = aw[(2*j2)*16 + k];
        s_aw2[j2*32 + 2*k+1] = aw[(2*j2+1)*16 + k]; }
    if (tid < 16){
        s_brz[2*tid]   = bih[tid]      + bhh[tid];
        s_brz[2*tid+1] = bih[tid+16]   + bhh[tid+16]; }
    if (tid < 8){
        s_bin[2*tid] = bih[32+2*tid]; s_bin[2*tid+1] = bih[33+2*tid];
        s_bhn[2*tid] = bhh[32+2*tid]; s_bhn[2*tid+1] = bhh[33+2*tid];
        s_offb2[tid] = offb[tid]; }
    if (tid < 4) s_ab2[tid] = ab[tid];
    __syncthreads();

    const int row = blockIdx.x * 128 + tid;
    int b = row / (8*HW);
    int rem = row - b * (8*HW);
    int head = rem / HW;
    int px = rem - head * HW;
    int y = px / WN, x = px - y * WN;

    float* np_ = g_net + (size_t)row * 16;
    ull hp[16];
    {
        const float4* gp = (const float4*)np_;
        float4 t0 = gp[0], t1 = gp[1], t2 = gp[2], t3 = gp[3];
        hp[0]=pk2(t0.x,t0.x); hp[1]=pk2(t0.y,t0.y); hp[2]=pk2(t0.z,t0.z); hp[3]=pk2(t0.w,t0.w);
        hp[4]=pk2(t1.x,t1.x); hp[5]=pk2(t1.y,t1.y); hp[6]=pk2(t1.z,t1.z); hp[7]=pk2(t1.w,t1.w);
        hp[8]=pk2(t2.x,t2.x); hp[9]=pk2(t2.y,t2.y); hp[10]=pk2(t2.z,t2.z); hp[11]=pk2(t2.w,t2.w);
        hp[12]=pk2(t3.x,t3.x); hp[13]=pk2(t3.y,t3.y); hp[14]=pk2(t3.z,t3.z); hp[15]=pk2(t3.w,t3.w);
    }
    float* op = g_off + (size_t)row * 8;
    float4 of0 = *(float4*)op, of1 = *(float4*)(op + 4);
    float ox = of0.x, oy = of0.y;

    float gx = -1.0f + x * (2.0f/95.0f);
    float gy = -1.0f + y * (2.0f/95.0f);
    float sgx = fminf(fmaxf(gx + ox, -1.0f), 1.0f);
    float sgy = fminf(fmaxf(gy + oy, -1.0f), 1.0f);
    float ix = (sgx + 1.0f) * 0.5f * 95.0f;
    float iy = (sgy + 1.0f) * 0.5f * 95.0f;
    float x0f = floorf(ix), y0f = floorf(iy);
    float wx = ix - x0f, wy = iy - y0f;
    int x0 = min(max((int)x0f, 0), 95), x1 = min(max((int)x0f + 1, 0), 95);
    int y0 = min(max((int)y0f, 0), 95), y1 = min(max((int)y0f + 1, 0), 95);
    const float* vb = g_vnear + ((size_t)(b*8 + head) * HW) * 16;
    float w00 = (1.f-wx)*(1.f-wy), w01 = wx*(1.f-wy), w10 = (1.f-wx)*wy, w11 = wx*wy;
    const float4* p00 = (const float4*)(vb + (y0*WN + x0)*16);
    const float4* p01 = (const float4*)(vb + (y0*WN + x1)*16);
    const float4* p10 = (const float4*)(vb + (y1*WN + x0)*16);
    const float4* p11 = (const float4*)(vb + (y1*WN + x1)*16);

    ull xp[18];
    #pragma unroll
    for (int k = 0; k < 4; k++){
        float4 a = p00[k], bq = p01[k], cc = p10[k], dd = p11[k];
        float s0 = w00*a.x + w01*bq.x + w10*cc.x + w11*dd.x;
        float s1 = w00*a.y + w01*bq.y + w10*cc.y + w11*dd.y;
        float s2 = w00*a.z + w01*bq.z + w10*cc.z + w11*dd.z;
        float s3 = w00*a.w + w01*bq.w + w10*cc.w + w11*dd.w;
        xp[4*k+0] = pk2(s0, s0); xp[4*k+1] = pk2(s1, s1);
        xp[4*k+2] = pk2(s2, s2); xp[4*k+3] = pk2(s3, s3);
    }
    xp[16] = pk2(ox, ox); xp[17] = pk2(oy, oy);

    float hn[16];
    #pragma unroll
    for (int g2 = 0; g2 < 8; g2++){
        float r0, z0, r1, z1;
        #pragma unroll
        for (int e = 0; e < 2; e++){
            int g = 2*g2 + e;
            ull acc = *(const ull*)(s_brz + 2*g);
            const ulonglong2* wi = (const ulonglong2*)(s_wiRZ + g*36);
            #pragma unroll
            for (int k2 = 0; k2 < 9; k2++){
                ulonglong2 w = wi[k2];
                acc = ffma2(xp[2*k2], w.x, acc);
                acc = ffma2(xp[2*k2+1], w.y, acc);
            }
            const ulonglong2* wh = (const ulonglong2*)(s_whRZ + g*32);
            #pragma unroll
            for (int k2 = 0; k2 < 8; k2++){
                ulonglong2 w = wh[k2];
                acc = ffma2(hp[2*k2], w.x, acc);
                acc = ffma2(hp[2*k2+1], w.y, acc);
            }
            float sr, sz; upk2(acc, sr, sz);
            if (e == 0){ r0 = sigmoidf_(sr); z0 = sigmoidf_(sz); }
            else       { r1 = sigmoidf_(sr); z1 = sigmoidf_(sz); }
        }
        ull acci = *(const ull*)(s_bin + 2*g2);
        const ulonglong2* wi2 = (const ulonglong2*)(s_wiNN + g2*36);
        #pragma unroll
        for (int k2 = 0; k2 < 9; k2++){
            ulonglong2 w = wi2[k2];
            acci = ffma2(xp[2*k2], w.x, acci);
            acci = ffma2(xp[2*k2+1], w.y, acci);
        }
        ull acch = *(const ull*)(s_bhn + 2*g2);
        const ulonglong2* wh2 = (const ulonglong2*)(s_whNN + g2*32);
        #pragma unroll
        for (int k2 = 0; k2 < 8; k2++){
            ulonglong2 w = wh2[k2];
            acch = ffma2(hp[2*k2], w.x, acch);
            acch = ffma2(hp[2*k2+1], w.y, acch);
        }
        float i0, i1, hh0, hh1, h0s, h1s, du;
        upk2(acci, i0, i1); upk2(acch, hh0, hh1);
        upk2(hp[2*g2], h0s, du); upk2(hp[2*g2+1], h1s, du);
        float n0 = tanhf(i0 + r0*hh0);
        float n1 = tanhf(i1 + r1*hh1);
        hn[2*g2]   = n0 + z0*(h0s - n0);
        hn[2*g2+1] = n1 + z1*(h1s - n1);
    }
    {
        float4* gp = (float4*)np_;
        gp[0] = make_float4(hn[0], hn[1], hn[2], hn[3]);
        gp[1] = make_float4(hn[4], hn[5], hn[6], hn[7]);
        gp[2] = make_float4(hn[8], hn[9], hn[10], hn[11]);
        gp[3] = make_float4(hn[12], hn[13], hn[14], hn[15]);
    }
    ull hnp[16];
    #pragma unroll
    for (int k = 0; k < 16; k++) hnp[k] = pk2(hn[k], hn[k]);

    #pragma unroll
    for (int j2 = 0; j2 < 4; j2++){
        ull acc = *(const ull*)(s_offb2 + 2*j2);
        const ulonglong2* w2 = (const ulonglong2*)(s_offw2 + j2*32);
        #pragma unroll
        for (int k2 = 0; k2 < 8; k2++){
            ulonglong2 w = w2[k2];
            acc = ffma2(hnp[2*k2], w.x, acc);
            acc = ffma2(hnp[2*k2+1], w.y, acc);
        }
        float d0, d1; upk2(acc, d0, d1);
        if (j2 == 0){ of0.x += d0; of0.y += d1; }
        else if (j2 == 1){ of0.z += d0; of0.w += d1; }
        else if (j2 == 2){ of1.x += d0; of1.y += d1; }
        else { of1.z += d0; of1.w += d1; }
    }
    *(float4*)op = of0; *(float4*)(op + 4) = of1;

    float4 av = *(float4*)(g_attn + (size_t)row * 4);
    #pragma unroll
    for (int j2 = 0; j2 < 2; j2++){
        ull acc = *(const ull*)(s_ab2 + 2*j2);
        const ulonglong2* w2 = (const ulonglong2*)(s_aw2 + j2*32);
        #pragma unroll
        for (int k2 = 0; k2 < 8; k2++){
            ulonglong2 w = w2[k2];
            acc = ffma2(hnp[2*k2], w.x, acc);
            acc = ffma2(hnp[2*k2+1], w.y, acc);
        }
        float d0, d1; upk2(acc, d0, d1);
        if (j2 == 0){ av.x += d0; av.y += d1; }
        else        { av.z += d0; av.w += d1; }
    }
    *(float4*)(g_attn + (size_t)row * 4) = av;
}

// ---------------- final: softmax + entropy + deformable gather (fp16 v) ----------------
__global__ void __launch_bounds__(256) final_k()
{
    int row = blockIdx.x * 256 + threadIdx.x;
    int b = row / (8*HW);
    int rem = row - b * (8*HW);
    int head = rem / HW;
    int px = rem - head * HW;
    int y = px / WN, x = px - y * WN;

    float4 av = *(const float4*)(g_attn + (size_t)row * 4);
    float ap[4] = {av.x, av.y, av.z, av.w};
    const float* tbp = g_tbias + (b*8 + head)*4;
    float tn[4] = {tbp[0], tbp[1], tbp[2], tbp[3]};

    float m = -1e30f;
    #pragma unroll
    for (int n = 0; n < 4; n++)
        #pragma unroll
        for (int p = 0; p < 4; p++) m = fmaxf(m, ap[p] + tn[n]);
    float pr[4][4]; float ssum = 0.0f;
    #pragma unroll
    for (int n = 0; n < 4; n++)
        #pragma unroll
        for (int p = 0; p < 4; p++){
            float e = expf(ap[p] + tn[n] - m);
            pr[n][p] = e; ssum += e;
        }
    float inv = 1.0f / ssum;
    float ent = 0.0f;
    #pragma unroll
    for (int n = 0; n < 4; n++)
        #pragma unroll
        for (int p = 0; p < 4; p++){
            float a = pr[n][p] * inv;
            pr[n][p] = a;
            ent -= a * logf(a + 1e-8f);
        }
    g_ent[row] = ent;

    float offs[8];
    {
        const float4* of = (const float4*)(g_off + (size_t)row * 8);
        float4 o0 = of[0], o1 = of[1];
        offs[0]=o0.x; offs[1]=o0.y; offs[2]=o0.z; offs[3]=o0.w;
        offs[4]=o1.x; offs[5]=o1.y; offs[6]=o1.z; offs[7]=o1.w;
    }
    float gx = -1.0f + x * (2.0f/95.0f);
    float gy = -1.0f + y * (2.0f/95.0f);
    float acc[16];
    #pragma unroll
    for (int k = 0; k < 16; k++) acc[k] = 0.0f;
    size_t vhbase = ((size_t)b*32 + head) * (size_t)(HW*8);

    #pragma unroll
    for (int p = 0; p < 4; p++){
        float sgx = fminf(fmaxf(gx + offs[2*p],   -1.0f), 1.0f);
        float sgy = fminf(fmaxf(gy + offs[2*p+1], -1.0f), 1.0f);
        float ix = (sgx + 1.0f) * 0.5f * 95.0f;
        float iy = (sgy + 1.0f) * 0.5f * 95.0f;
        float x0f = floorf(ix), y0f = floorf(iy);
        float wx = ix - x0f, wy = iy - y0f;
        int x0 = min(max((int)x0f, 0), 95), x1 = min(max((int)x0f + 1, 0), 95);
        int y0 = min(max((int)y0f, 0), 95), y1 = min(max((int)y0f + 1, 0), 95);
        int ti[4] = {(y0*WN+x0)*8, (y0*WN+x1)*8, (y1*WN+x0)*8, (y1*WN+x1)*8};
        float tw4[4] = {(1.f-wx)*(1.f-wy), wx*(1.f-wy), (1.f-wx)*wy, wx*wy};
        #pragma unroll
        for (int n = 0; n < 4; n++){
            const __half2* vbh = g_vh + vhbase + (size_t)n * (8*HW*8);
            float an = pr[n][p];
            #pragma unroll
            for (int t = 0; t < 4; t++){
                float cw = an * tw4[t];
                const uint4* pp = (const uint4*)(vbh + ti[t]);
                uint4 A = pp[0], Bv = pp[1];
                float2 f;
                f = __half22float2(*(__half2*)&A.x);  acc[0]  += cw*f.x; acc[1]  += cw*f.y;
                f = __half22float2(*(__half2*)&A.y);  acc[2]  += cw*f.x; acc[3]  += cw*f.y;
                f = __half22float2(*(__half2*)&A.z);  acc[4]  += cw*f.x; acc[5]  += cw*f.y;
                f = __half22float2(*(__half2*)&A.w);  acc[6]  += cw*f.x; acc[7]  += cw*f.y;
                f = __half22float2(*(__half2*)&Bv.x); acc[8]  += cw*f.x; acc[9]  += cw*f.y;
                f = __half22float2(*(__half2*)&Bv.y); acc[10] += cw*f.x; acc[11] += cw*f.y;
                f = __half22float2(*(__half2*)&Bv.z); acc[12] += cw*f.x; acc[13] += cw*f.y;
                f = __half22float2(*(__half2*)&Bv.w); acc[14] += cw*f.x; acc[15] += cw*f.y;
            }
        }
    }
    size_t ob = ((size_t)b*128 + head*16) * (size_t)HW + px;
    #pragma unroll
    for (int hd = 0; hd < 16; hd++)
        g_agg[ob + (size_t)hd * HW] = acc[hd];
}

// ---------------- entropy reduce over heads -> confidence ----------------
__global__ void __launch_bounds__(256) entconf_k(float* __restrict__ outp)
{
    int i = blockIdx.x * 256 + threadIdx.x;   // B*HW = 18432
    int b = i / HW, px = i - b * HW;
    float s = 0.0f;
    #pragma unroll
    for (int hh = 0; hh < 8; hh++) s += g_ent[((size_t)b*8 + hh)*HW + px];
    s *= 0.125f;
    float c = 1.0f - fminf(fmaxf(s * (1.0f/(2.772588722239781f + 1e-8f)), 0.0f), 1.0f);
    outp[2359296 + i] = c;
    outp[2359296 + 18432 + i] = s;
}

// ---------------- launch ----------------
extern "C" void kernel_launch(void* const* d_in, const int* in_sizes, int n_in,
                              void* d_out, int out_size)
{
    const float* query    = (const float*)d_in[0];
    const float* values   = (const float*)d_in[1];
    const float* rel_time = (const float*)d_in[2];
    const float* time_enc = (const float*)d_in[3];
    const float* qw  = (const float*)d_in[4];
    const float* qb  = (const float*)d_in[5];
    const float* vw  = (const float*)d_in[6];
    const float* vb  = (const float*)d_in[7];
    const float* dww = (const float*)d_in[8];
    const float* dwb = (const float*)d_in[9];
    const float* pww = (const float*)d_in[10];
    const float* pwb = (const float*)d_in[11];
    const float* wih = (const float*)d_in[12];
    const float* whh = (const float*)d_in[13];
    const float* bih = (const float*)d_in[14];
    const float* bhh = (const float*)d_in[15];
    const float* offw = (const float*)d_in[16];
    const float* offb = (const float*)d_in[17];
    const float* aw  = (const float*)d_in[18];
    const float* ab  = (const float*)d_in[19];
    const float* tw  = (const float*)d_in[20];
    const float* tb  = (const float*)d_in[21];
    const float* o1w = (const float*)d_in[22];
    const float* o1b = (const float*)d_in[23];
    const float* o2w = (const float*)d_in[24];
    const float* o2b = (const float*)d_in[25];
    const float* gate = (const float*)d_in[26];
    float* outp = (float*)d_out;

    float *qperm, *vnear, *dwtmp, *net, *agg, *tmp2;
    __half2* vh;
    cudaGetSymbolAddress((void**)&qperm, g_qperm);
    cudaGetSymbolAddress((void**)&vnear, g_vnear);
    cudaGetSymbolAddress((void**)&vh,    g_vh);
    cudaGetSymbolAddress((void**)&dwtmp, g_dwtmp);
    cudaGetSymbolAddress((void**)&net,   g_net);
    cudaGetSymbolAddress((void**)&agg,   g_agg);
    cudaGetSymbolAddress((void**)&tmp2,  g_tmp2);

    cudaFuncSetAttribute((const void*)conv1x1_k<1>, cudaFuncAttributeMaxDynamicSharedMemorySize, CONV_SMEM_BYTES);
    cudaFuncSetAttribute((const void*)conv1x1_k<2>, cudaFuncAttributeMaxDynamicSharedMemorySize, CONV_SMEM_BYTES);
    cudaFuncSetAttribute((const void*)conv1x1_k<3>, cudaFuncAttributeMaxDynamicSharedMemorySize, CONV_SMEM_BYTES);
    cudaFuncSetAttribute((const void*)conv_qv_k,    cudaFuncAttributeMaxDynamicSharedMemorySize, CONV_SMEM_BYTES);
    cudaFuncSetAttribute((const void*)convh_k,      cudaFuncAttributeMaxDynamicSharedMemorySize, CONVH_SMEM_BYTES);

    prep_k<<<1, 64>>>(rel_time, time_enc, tw, tb);
    conv_qv_k   <<<dim3(144, 4),     128, CONV_SMEM_BYTES>>>(query, qw, qb, qperm,
                                                             values, vw, vb, vnear);
    convh_k     <<<dim3(72, NB*NF),  256, CONVH_SMEM_BYTES>>>(values, vw, vb, vh);
    dwconv_k    <<<dim3(6, NB*CC), dim3(96, 4)>>>(query, dww, dwb, dwtmp);
    conv1x1_k<3><<<dim3(144, NB),    128, CONV_SMEM_BYTES>>>(dwtmp,  pww, pwb, net,   nullptr);
    corr_k      <<<576, 256>>>();
    for (int it = 0; it < 3; it++)
        gru_k   <<<1152, 128>>>(wih, whh, bih, bhh, offw, offb, aw, ab);
    final_k     <<<576, 256>>>();
    conv1x1_k<1><<<dim3(144, NB),    128, CONV_SMEM_BYTES>>>(agg,  o1w, o1b, tmp2, nullptr);
    conv1x1_k<2><<<dim3(144, NB),    128, CONV_SMEM_BYTES>>>(tmp2, o2w, o2b, outp, gate);
    entconf_k   <<<72, 256>>>(outp);
}

// round 15
// speedup vs baseline: 1.2149x; 1.2149x over previous
#include <cuda_runtime.h>
#include <cuda_fp16.h>
#include <math.h>

#define HW 9216
#define WN 96
#define NB 2
#define NF 4
#define NH 8
#define CC 128

typedef unsigned long long ull;

// ---------------- scratch (device globals; no allocation allowed) ----------------
__device__ float   g_qperm[2359296];   // [B, HEADS, HW, 16]
__device__ float   g_vnear[2359296];   // [B, HEADS, HW, 16]  (fp32 nearest frame)
__device__ __half2 g_vh  [4718592];    // fp16 all frames: [(b*4+n)*8+head][hw][8 half2]
__device__ float   g_dwtmp[2359296];   // [B, C, HW]
__device__ float   g_net  [2359296];   // [B*HEADS*HW, 16]
__device__ float   g_off  [1179648];   // [B*HEADS*HW, P, 2]
__device__ float   g_attn [589824];    // [B*HEADS*HW, P]
__device__ float   g_agg  [2359296];   // [B, C, HW]
__device__ float   g_tmp2 [2359296];   // [B, C, HW]
__device__ float   g_ent  [147456];    // [B*HEADS*HW]
__device__ float   g_tbias[64];        // [B, HEADS, N]
__device__ int     g_nearest[2];

// ---------------- helpers ----------------
__device__ __forceinline__ float geluf(float v){
    return 0.5f * v * (1.0f + erff(v * 0.70710678118654752f));
}
__device__ __forceinline__ float sigmoidf_(float v){
    return 1.0f / (1.0f + expf(-v));
}
__device__ __forceinline__ ull pk2(float x, float y){
    ull r;
    asm("mov.b64 %0, {%1,%2};" : "=l"(r) : "f"(x), "f"(y));
    return r;
}
__device__ __forceinline__ void upk2(ull v, float& x, float& y){
    asm("mov.b64 {%0,%1}, %2;" : "=f"(x), "=f"(y) : "l"(v));
}
__device__ __forceinline__ ull ffma2(ull a, ull b, ull c){
    ull d;
    asm("fma.rn.f32x2 %0, %1, %2, %3;" : "=l"(d) : "l"(a), "l"(b), "l"(c));
    return d;
}
__device__ __forceinline__ unsigned smem_u32(const void* p){
    return (unsigned)__cvta_generic_to_shared(p);
}

// ---------------- conv1x1 as tiled GEMM (fp32 FFMA2, R11 4x8 microtile, 256 thr) ----------------
// MODE: 1 = NCHW out + gelu, 2 = NCHW out * sigmoid(gate),
//       3 = head-permuted out (no act), 4 = like 3 but input frame = nearest (per b)
static constexpr int CONV_SMEM_BYTES = (128*132 + 64*132) * 4;  // 101376 B

template<int MODE>
__global__ void __launch_bounds__(256, 2) conv1x1_k(
    const float* __restrict__ in, const float* __restrict__ wgt,
    const float* __restrict__ bias, float* __restrict__ out,
    const float* __restrict__ gate)
{
    extern __shared__ float sm[];
    float* sW = sm;               // [c][o] pitch 132
    float* sB = sm + 128*132;     // in tile [c][64] then stage [px][o] pitch 132
    const int tid = threadIdx.x;
    const int img = blockIdx.y;
    const int px0 = blockIdx.x * 64;
    size_t in_img = (size_t)img;
    if (MODE == 4) in_img = (size_t)(img*4 + g_nearest[img]);
    const float* inp = in + in_img * (128*HW) + px0;

    #pragma unroll 8
    for (int i = tid; i < 16384; i += 256){
        int o = i >> 7, c = i & 127;
        sW[c*132 + o] = wgt[i];
    }
    #pragma unroll 8
    for (int i = tid; i < 8192; i += 256){
        int c = i >> 6, p = i & 63;
        sB[c*64 + p] = inp[(size_t)c*HW + p];
    }
    __syncthreads();

    const int px4 = (tid & 15) * 4;
    const int o8  = (tid >> 4) * 8;
    ull acc[4][4];
    #pragma unroll
    for (int i = 0; i < 4; i++)
        #pragma unroll
        for (int j = 0; j < 4; j++) acc[i][j] = 0ull;

    #pragma unroll 4
    for (int c = 0; c < 128; c++){
        float4 a = *(const float4*)(sB + c*64 + px4);
        ulonglong2 w0 = *(const ulonglong2*)(sW + c*132 + o8);
        ulonglong2 w1 = *(const ulonglong2*)(sW + c*132 + o8 + 4);
        ull a0 = pk2(a.x, a.x), a1 = pk2(a.y, a.y);
        ull a2 = pk2(a.z, a.z), a3 = pk2(a.w, a.w);
        acc[0][0] = ffma2(a0, w0.x, acc[0][0]); acc[0][1] = ffma2(a0, w0.y, acc[0][1]);
        acc[0][2] = ffma2(a0, w1.x, acc[0][2]); acc[0][3] = ffma2(a0, w1.y, acc[0][3]);
        acc[1][0] = ffma2(a1, w0.x, acc[1][0]); acc[1][1] = ffma2(a1, w0.y, acc[1][1]);
        acc[1][2] = ffma2(a1, w1.x, acc[1][2]); acc[1][3] = ffma2(a1, w1.y, acc[1][3]);
        acc[2][0] = ffma2(a2, w0.x, acc[2][0]); acc[2][1] = ffma2(a2, w0.y, acc[2][1]);
        acc[2][2] = ffma2(a2, w1.x, acc[2][2]); acc[2][3] = ffma2(a2, w1.y, acc[2][3]);
        acc[3][0] = ffma2(a3, w0.x, acc[3][0]); acc[3][1] = ffma2(a3, w0.y, acc[3][1]);
        acc[3][2] = ffma2(a3, w1.x, acc[3][2]); acc[3][3] = ffma2(a3, w1.y, acc[3][3]);
    }
    __syncthreads();

    float bl[8];
    #pragma unroll
    for (int j = 0; j < 8; j++) bl[j] = bias[o8 + j];
    float gl[8];
    if (MODE == 2){
        #pragma unroll
        for (int j = 0; j < 8; j++) gl[j] = sigmoidf_(gate[o8 + j]);
    }

    #pragma unroll
    for (int i = 0; i < 4; i++){
        #pragma unroll
        for (int j2 = 0; j2 < 4; j2++){
            float v0, v1;
            upk2(acc[i][j2], v0, v1);
            int j = j2 * 2;
            v0 += bl[j]; v1 += bl[j+1];
            if (MODE == 1){ v0 = geluf(v0); v1 = geluf(v1); }
            if (MODE == 2){ v0 *= gl[j]; v1 *= gl[j+1]; }
            sB[(px4+i)*132 + o8 + j    ] = v0;
            sB[(px4+i)*132 + o8 + j + 1] = v1;
        }
    }
    __syncthreads();

    if (MODE >= 3){
        #pragma unroll 8
        for (int i = tid; i < 8192; i += 256){
            int head = i >> 10, local = i & 1023;
            int px = local >> 4;
            out[(((size_t)img*8 + head)*HW + px0)*16 + local] = sB[px*132 + head*16 + (local & 15)];
        }
    } else {
        #pragma unroll 8
        for (int i = tid; i < 8192; i += 256){
            int o = i >> 6, p = i & 63;
            out[(size_t)img*(128*HW) + (size_t)o*HW + px0 + p] = sB[p*132 + o];
        }
    }
}

// ---------------- fp16 tensor-core conv1x1: all-frames v -> g_vh only ----------------
static constexpr int CONVH_SMEM_BYTES = 2 * 128 * 136 * 2;  // 69632 B

__global__ void __launch_bounds__(256, 2) convh_k(
    const float* __restrict__ in, const float* __restrict__ wgt,
    const float* __restrict__ bias, __half2* __restrict__ out)
{
    extern __shared__ __half sh[];
    __half* sA = sh;              // [c][px] pitch 136
    __half* sB = sh + 128*136;    // [o][c] pitch 136
    const int tid = threadIdx.x;
    const int img = blockIdx.y;
    const int px0 = blockIdx.x * 128;
    const float* inp = in + (size_t)img * (128*HW) + px0;

    #pragma unroll 8
    for (int i = tid; i < 4096; i += 256){
        int c = i >> 5, p4 = (i & 31) * 4;
        float4 v = *(const float4*)(inp + (size_t)c*HW + p4);
        __half2* d = (__half2*)(sA + c*136 + p4);
        d[0] = __floats2half2_rn(v.x, v.y);
        d[1] = __floats2half2_rn(v.z, v.w);
    }
    #pragma unroll 8
    for (int i = tid; i < 4096; i += 256){
        int o = i >> 5, c4 = (i & 31) * 4;
        float4 v = *(const float4*)(wgt + o*128 + c4);
        __half2* d = (__half2*)(sB + o*136 + c4);
        d[0] = __floats2half2_rn(v.x, v.y);
        d[1] = __floats2half2_rn(v.z, v.w);
    }
    __syncthreads();

    const int wid = tid >> 5, lane = tid & 31;
    const int px_w = (wid & 1) * 64;
    const int o_w  = (wid >> 1) * 32;
    const int lr = lane & 7, lg = lane >> 3;

    float acc[4][4][4];
    #pragma unroll
    for (int m = 0; m < 4; m++)
        #pragma unroll
        for (int n = 0; n < 4; n++)
            #pragma unroll
            for (int r = 0; r < 4; r++) acc[m][n][r] = 0.0f;

    #pragma unroll
    for (int k0 = 0; k0 < 128; k0 += 16){
        unsigned a[4][4], b[4][2];
        #pragma unroll
        for (int mt = 0; mt < 4; mt++){
            int px = px_w + mt*16 + ((lg & 1) ? 8 : 0);
            int kk = k0 + lr + ((lg & 2) ? 8 : 0);
            unsigned addr = smem_u32(sA + kk*136 + px);
            asm volatile("ldmatrix.sync.aligned.m8n8.x4.trans.shared.b16 {%0,%1,%2,%3}, [%4];"
                : "=r"(a[mt][0]), "=r"(a[mt][1]), "=r"(a[mt][2]), "=r"(a[mt][3]) : "r"(addr));
        }
        #pragma unroll
        for (int nt2 = 0; nt2 < 2; nt2++){
            int oo = o_w + nt2*16 + lr + ((lg & 2) ? 8 : 0);
            int kk = k0 + ((lg & 1) ? 8 : 0);
            unsigned addr = smem_u32(sB + oo*136 + kk);
            unsigned r0, r1, r2, r3;
            asm volatile("ldmatrix.sync.aligned.m8n8.x4.shared.b16 {%0,%1,%2,%3}, [%4];"
                : "=r"(r0), "=r"(r1), "=r"(r2), "=r"(r3) : "r"(addr));
            b[2*nt2][0] = r0;   b[2*nt2][1] = r1;
            b[2*nt2+1][0] = r2; b[2*nt2+1][1] = r3;
        }
        #pragma unroll
        for (int mt = 0; mt < 4; mt++)
            #pragma unroll
            for (int nt = 0; nt < 4; nt++){
                asm volatile(
                    "mma.sync.aligned.m16n8k16.row.col.f32.f16.f16.f32 "
                    "{%0,%1,%2,%3}, {%4,%5,%6,%7}, {%8,%9}, {%0,%1,%2,%3};"
                    : "+f"(acc[mt][nt][0]), "+f"(acc[mt][nt][1]),
                      "+f"(acc[mt][nt][2]), "+f"(acc[mt][nt][3])
                    : "r"(a[mt][0]), "r"(a[mt][1]), "r"(a[mt][2]), "r"(a[mt][3]),
                      "r"(b[nt][0]), "r"(b[nt][1]));
            }
    }

    float bl[4][2];
    #pragma unroll
    for (int nt = 0; nt < 4; nt++){
        int o = o_w + nt*8 + (lane & 3)*2;
        bl[nt][0] = bias[o]; bl[nt][1] = bias[o+1];
    }
    #pragma unroll
    for (int mt = 0; mt < 4; mt++){
        int pxr = px0 + px_w + mt*16 + (lane >> 2);
        #pragma unroll
        for (int nt = 0; nt < 4; nt++){
            int o = o_w + nt*8 + (lane & 3)*2;
            int head = o >> 4, pr = (o & 15) >> 1;
            __half2 h0 = __floats2half2_rn(acc[mt][nt][0] + bl[nt][0], acc[mt][nt][1] + bl[nt][1]);
            __half2 h1 = __floats2half2_rn(acc[mt][nt][2] + bl[nt][0], acc[mt][nt][3] + bl[nt][1]);
            size_t base = ((size_t)(img*8 + head)*HW);
            out[(base + pxr    )*8 + pr] = h0;
            out[(base + pxr + 8)*8 + pr] = h1;
        }
    }
}

// ---------------- depthwise 7x7 + gelu (smem-tiled) ----------------
__global__ void __launch_bounds__(384) dwconv_k(
    const float* __restrict__ q, const float* __restrict__ dww,
    const float* __restrict__ dwb, float* __restrict__ out)
{
    __shared__ float swm[49];
    __shared__ float tile[22*104];
    const int plane = blockIdx.y;
    const int c = plane & 127;
    const int ty0 = blockIdx.x * 16;
    const int tid = threadIdx.y * 96 + threadIdx.x;
    if (tid < 49) swm[tid] = dww[c*49 + tid];
    const float* qp = q + (size_t)plane * HW;
    for (int i = tid; i < 22*104; i += 384){
        int r = i / 104, xc = i - r*104;
        int gy = ty0 - 3 + r, gx = xc - 3;
        float v = 0.0f;
        if ((unsigned)gy < 96u && (unsigned)gx < 96u) v = qp[gy*WN + gx];
        tile[i] = v;
    }
    __syncthreads();

    float w[49];
    #pragma unroll
    for (int i = 0; i < 49; i++) w[i] = swm[i];

    const int tx = threadIdx.x;
    const int ly0 = threadIdx.y * 4;
    float acc[4];
    float bb = dwb[c];
    #pragma unroll
    for (int o = 0; o < 4; o++) acc[o] = bb;

    #pragma unroll
    for (int r = 0; r < 10; r++){
        float in7[7];
        #pragma unroll
        for (int j = 0; j < 7; j++) in7[j] = tile[(ly0 + r)*104 + tx + j];
        #pragma unroll
        for (int o = 0; o < 4; o++){
            int ky = r - o;
            if (ky >= 0 && ky <= 6){
                #pragma unroll
                for (int kx = 0; kx < 7; kx++)
                    acc[o] += in7[kx] * w[ky*7 + kx];
            }
        }
    }
    #pragma unroll
    for (int o = 0; o < 4; o++){
        int gy = ty0 + ly0 + o;
        out[(size_t)plane*HW + gy*WN + tx] = geluf(acc[o]);
    }
}

// ---------------- prep: nearest idx + time bias ----------------
__global__ void prep_k(const float* __restrict__ rel_time, const float* __restrict__ time_enc,
                       const float* __restrict__ tw, const float* __restrict__ tb)
{
    int t = threadIdx.x;
    if (t < 2){
        int best = 0; float bv = fabsf(rel_time[t*4]);
        for (int n = 1; n < 4; n++){
            float v = fabsf(rel_time[t*4 + n]);
            if (v < bv){ bv = v; best = n; }
        }
        g_nearest[t] = best;
    }
    if (t < 64){
        int b = t >> 5, rem = t & 31, head = rem >> 2, n = rem & 3;
        float s = tb[head];
        for (int tc = 0; tc < 64; tc++)
            s += time_enc[(b*4 + n)*64 + tc] * tw[head*64 + tc];
        g_tbias[(b*8 + head)*4 + n] = s;
    }
}

// ---------------- correlation argmax -> initial offsets ----------------
__global__ void __launch_bounds__(256) corr_k()
{
    int row = blockIdx.x * 256 + threadIdx.x;
    int b = row / (8*HW);
    int rem = row - b * (8*HW);
    int head = rem / HW;
    int px = rem - head * HW;
    int y = px / WN, x = px - y * WN;
    const float4* qv = (const float4*)(g_qperm + (size_t)row * 16);
    float4 q0 = qv[0], q1 = qv[1], q2 = qv[2], q3 = qv[3];
    const float* vb = g_vnear + ((size_t)(b*8 + head) * HW) * 16;
    const int sdx[5] = {0, -1, 1, 0, 0};
    const int sdy[5] = {0,  0, 0,-1, 1};
    int best = 0; float bs = 0.0f;
    #pragma unroll
    for (int s = 0; s < 5; s++){
        int yy = y - sdy[s], xx = x - sdx[s];
        float sc = 0.0f;
        if ((unsigned)yy < 96u && (unsigned)xx < 96u){
            const float4* vv = (const float4*)(vb + (yy*WN + xx)*16);
            float4 v0 = vv[0], v1 = vv[1], v2 = vv[2], v3 = vv[3];
            sc = q0.x*v0.x + q0.y*v0.y + q0.z*v0.z + q0.w*v0.w
               + q1.x*v1.x + q1.y*v1.y + q1.z*v1.z + q1.w*v1.w
               + q2.x*v2.x + q2.y*v2.y + q2.z*v2.z + q2.w*v2.w
               + q3.x*v3.x + q3.y*v3.y + q3.z*v3.z + q3.w*v3.w;
        }
        if (s == 0){ bs = sc; }
        else if (sc > bs){ bs = sc; best = s; }
    }
    float offx = sdy[best] * (2.0f/96.0f);
    float offy = sdx[best] * (2.0f/96.0f);
    float* op = g_off + (size_t)row * 8;
    #pragma unroll
    for (int p = 0; p < 4; p++){ op[2*p] = offx; op[2*p+1] = offy; }
    *(float4*)(g_attn + (size_t)row * 4) = make_float4(0.f, 0.f, 0.f, 0.f);
}

// ---------------- GRU iteration (packed FFMA2) ----------------
__global__ void __launch_bounds__(128, 3) gru_k(
    const float* __restrict__ wih, const float* __restrict__ whh,
    const float* __restrict__ bih, const float* __restrict__ bhh,
    const float* __restrict__ offw, const float* __restrict__ offb,
    const float* __restrict__ aw, const float* __restrict__ ab)
{
    __shared__ __align__(16) float s_wiRZ[576];
    __shared__ __align__(16) float s_whRZ[512];
    __shared__ __align__(16) float s_wiNN[288];
    __shared__ __align__(16) float s_whNN[256];
    __shared__ __align__(16) float s_offw2[128];
    __shared__ __align__(16) float s_aw2[64];
    __shared__ __align__(16) float s_brz[32];
    __shared__ __align__(16) float s_bin[16];
    __shared__ __align__(16) float s_bhn[16];
    __shared__ __align__(16) float s_offb2[8];
    __shared__ __align__(16) float s_ab2[8];
    const int tid = threadIdx.x;
    for (int i = tid; i < 288; i += 128){ int g = i/18, k = i - g*18;
        s_wiRZ[g*36 + 2*k]   = wih[g*18 + k];
        s_wiRZ[g*36 + 2*k+1] = wih[(g+16)*18 + k]; }
    for (int i = tid; i < 256; i += 128){ int g = i >> 4, k = i & 15;
        s_whRZ[g*32 + 2*k]   = whh[g*16 + k];
        s_whRZ[g*32 + 2*k+1] = whh[(g+16)*16 + k]; }
    for (int i = tid; i < 144; i += 128){ int g2 = i/18, k = i - g2*18;
        s_wiNN[g2*36 + 2*k]   = wih[(32+2*g2)*18 + k];
        s_wiNN[g2*36 + 2*k+1] = wih[(33+2*g2)*18 + k]; }
    if (tid < 128){ int g2 = tid >> 4, k = tid & 15;
        s_whNN[g2*32 + 2*k]   = whh[(32+2*g2)*16 + k];
        s_whNN[g2*32 + 2*k+1] = whh[(33+2*g2)*16 + k]; }
    if (tid < 64){ int j2 = tid >> 4, k = tid & 15;
        s_offw2[j2*32 + 2*k]   = offw[(2*j2)*16 + k];
        s_offw2[j2*32 + 2*k+1] = offw[(2*j2+1)*16 + k]; }
    if (tid < 32){ int j2 = tid >> 4, k = tid & 15;
        s_aw2[j2*32 + 2*k]   = aw[(2*j2)*16 + k];
        s_aw2[j2*32 + 2*k+1] = aw[(2*j2+1)*16 + k]; }
    if (tid < 16){
        s_brz[2*tid]   = bih[tid]      + bhh[tid];
        s_brz[2*tid+1] = bih[tid+16]   + bhh[tid+16]; }
    if (tid < 8){
        s_bin[2*tid] = bih[32+2*tid]; s_bin[2*tid+1] = bih[33+2*tid];
        s_bhn[2*tid] = bhh[32+2*tid]; s_bhn[2*tid+1] = bhh[33+2*tid];
        s_offb2[tid] = offb[tid]; }
    if (tid < 4) s_ab2[tid] = ab[tid];
    __syncthreads();

    const int row = blockIdx.x * 128 + tid;
    int b = row / (8*HW);
    int rem = row - b * (8*HW);
    int head = rem / HW;
    int px = rem - head * HW;
    int y = px / WN, x = px - y * WN;

    float* np_ = g_net + (size_t)row * 16;
    ull hp[16];
    {
        const float4* gp = (const float4*)np_;
        float4 t0 = gp[0], t1 = gp[1], t2 = gp[2], t3 = gp[3];
        hp[0]=pk2(t0.x,t0.x); hp[1]=pk2(t0.y,t0.y); hp[2]=pk2(t0.z,t0.z); hp[3]=pk2(t0.w,t0.w);
        hp[4]=pk2(t1.x,t1.x); hp[5]=pk2(t1.y,t1.y); hp[6]=pk2(t1.z,t1.z); hp[7]=pk2(t1.w,t1.w);
        hp[8]=pk2(t2.x,t2.x); hp[9]=pk2(t2.y,t2.y); hp[10]=pk2(t2.z,t2.z); hp[11]=pk2(t2.w,t2.w);
        hp[12]=pk2(t3.x,t3.x); hp[13]=pk2(t3.y,t3.y); hp[14]=pk2(t3.z,t3.z); hp[15]=pk2(t3.w,t3.w);
    }
    float* op = g_off + (size_t)row * 8;
    float4 of0 = *(float4*)op, of1 = *(float4*)(op + 4);
    float ox = of0.x, oy = of0.y;

    float gx = -1.0f + x * (2.0f/95.0f);
    float gy = -1.0f + y * (2.0f/95.0f);
    float sgx = fminf(fmaxf(gx + ox, -1.0f), 1.0f);
    float sgy = fminf(fmaxf(gy + oy, -1.0f), 1.0f);
    float ix = (sgx + 1.0f) * 0.5f * 95.0f;
    float iy = (sgy + 1.0f) * 0.5f * 95.0f;
    float x0f = floorf(ix), y0f = floorf(iy);
    float wx = ix - x0f, wy = iy - y0f;
    int x0 = min(max((int)x0f, 0), 95), x1 = min(max((int)x0f + 1, 0), 95);
    int y0 = min(max((int)y0f, 0), 95), y1 = min(max((int)y0f + 1, 0), 95);
    const float* vb = g_vnear + ((size_t)(b*8 + head) * HW) * 16;
    float w00 = (1.f-wx)*(1.f-wy), w01 = wx*(1.f-wy), w10 = (1.f-wx)*wy, w11 = wx*wy;
    const float4* p00 = (const float4*)(vb + (y0*WN + x0)*16);
    const float4* p01 = (const float4*)(vb + (y0*WN + x1)*16);
    const float4* p10 = (const float4*)(vb + (y1*WN + x0)*16);
    const float4* p11 = (const float4*)(vb + (y1*WN + x1)*16);

    ull xp[18];
    #pragma unroll
    for (int k = 0; k < 4; k++){
        float4 a = p00[k], bq = p01[k], cc = p10[k], dd = p11[k];
        float s0 = w00*a.x + w01*bq.x + w10*cc.x + w11*dd.x;
        float s1 = w00*a.y + w01*bq.y + w10*cc.y + w11*dd.y;
        float s2 = w00*a.z + w01*bq.z + w10*cc.z + w11*dd.z;
        float s3 = w00*a.w + w01*bq.w + w10*cc.w + w11*dd.w;
        xp[4*k+0] = pk2(s0, s0); xp[4*k+1] = pk2(s1, s1);
        xp[4*k+2] = pk2(s2, s2); xp[4*k+3] = pk2(s3, s3);
    }
    xp[16] = pk2(ox, ox); xp[17] = pk2(oy, oy);

    float hn[16];
    #pragma unroll
    for (int g2 = 0; g2 < 8; g2++){
        float r0, z0, r1, z1;
        #pragma unroll
        for (int e = 0; e < 2; e++){
            int g = 2*g2 + e;
            ull acc = *(const ull*)(s_brz + 2*g);
            const ulonglong2* wi = (const ulonglong2*)(s_wiRZ + g*36);
            #pragma unroll
            for (int k2 = 0; k2 < 9; k2++){
                ulonglong2 w = wi[k2];
                acc = ffma2(xp[2*k2], w.x, acc);
                acc = ffma2(xp[2*k2+1], w.y, acc);
            }
            const ulonglong2* wh = (const ulonglong2*)(s_whRZ + g*32);
            #pragma unroll
            for (int k2 = 0; k2 < 8; k2++){
                ulonglong2 w = wh[k2];
                acc = ffma2(hp[2*k2], w.x, acc);
                acc = ffma2(hp[2*k2+1], w.y, acc);
            }
            float sr, sz; upk2(acc, sr, sz);
            if (e == 0){ r0 = sigmoidf_(sr); z0 = sigmoidf_(sz); }
            else       { r1 = sigmoidf_(sr); z1 = sigmoidf_(sz); }
        }
        ull acci = *(const ull*)(s_bin + 2*g2);
        const ulonglong2* wi2 = (const ulonglong2*)(s_wiNN + g2*36);
        #pragma unroll
        for (int k2 = 0; k2 < 9; k2++){
            ulonglong2 w = wi2[k2];
            acci = ffma2(xp[2*k2], w.x, acci);
            acci = ffma2(xp[2*k2+1], w.y, acci);
        }
        ull acch = *(const ull*)(s_bhn + 2*g2);
        const ulonglong2* wh2 = (const ulonglong2*)(s_whNN + g2*32);
        #pragma unroll
        for (int k2 = 0; k2 < 8; k2++){
            ulonglong2 w = wh2[k2];
            acch = ffma2(hp[2*k2], w.x, acch);
            acch = ffma2(hp[2*k2+1], w.y, acch);
        }
        float i0, i1, hh0, hh1, h0s, h1s, du;
        upk2(acci, i0, i1); upk2(acch, hh0, hh1);
        upk2(hp[2*g2], h0s, du); upk2(hp[2*g2+1], h1s, du);
        float n0 = tanhf(i0 + r0*hh0);
        float n1 = tanhf(i1 + r1*hh1);
        hn[2*g2]   = n0 + z0*(h0s - n0);
        hn[2*g2+1] = n1 + z1*(h1s - n1);
    }
    {
        float4* gp = (float4*)np_;
        gp[0] = make_float4(hn[0], hn[1], hn[2], hn[3]);
        gp[1] = make_float4(hn[4], hn[5], hn[6], hn[7]);
        gp[2] = make_float4(hn[8], hn[9], hn[10], hn[11]);
        gp[3] = make_float4(hn[12], hn[13], hn[14], hn[15]);
    }
    ull hnp[16];
    #pragma unroll
    for (int k = 0; k < 16; k++) hnp[k] = pk2(hn[k], hn[k]);

    #pragma unroll
    for (int j2 = 0; j2 < 4; j2++){
        ull acc = *(const ull*)(s_offb2 + 2*j2);
        const ulonglong2* w2 = (const ulonglong2*)(s_offw2 + j2*32);
        #pragma unroll
        for (int k2 = 0; k2 < 8; k2++){
            ulonglong2 w = w2[k2];
            acc = ffma2(hnp[2*k2], w.x, acc);
            acc = ffma2(hnp[2*k2+1], w.y, acc);
        }
        float d0, d1; upk2(acc, d0, d1);
        if (j2 == 0){ of0.x += d0; of0.y += d1; }
        else if (j2 == 1){ of0.z += d0; of0.w += d1; }
        else if (j2 == 2){ of1.x += d0; of1.y += d1; }
        else { of1.z += d0; of1.w += d1; }
    }
    *(float4*)op = of0; *(float4*)(op + 4) = of1;

    float4 av = *(float4*)(g_attn + (size_t)row * 4);
    #pragma unroll
    for (int j2 = 0; j2 < 2; j2++){
        ull acc = *(const ull*)(s_ab2 + 2*j2);
        const ulonglong2* w2 = (const ulonglong2*)(s_aw2 + j2*32);
        #pragma unroll
        for (int k2 = 0; k2 < 8; k2++){
            ulonglong2 w = w2[k2];
            acc = ffma2(hnp[2*k2], w.x, acc);
            acc = ffma2(hnp[2*k2+1], w.y, acc);
        }
        float d0, d1; upk2(acc, d0, d1);
        if (j2 == 0){ av.x += d0; av.y += d1; }
        else        { av.z += d0; av.w += d1; }
    }
    *(float4*)(g_attn + (size_t)row * 4) = av;
}

// ---------------- final: softmax + entropy + deformable gather (fp16 v) ----------------
__global__ void __launch_bounds__(256) final_k()
{
    int row = blockIdx.x * 256 + threadIdx.x;
    int b = row / (8*HW);
    int rem = row - b * (8*HW);
    int head = rem / HW;
    int px = rem - head * HW;
    int y = px / WN, x = px - y * WN;

    float4 av = *(const float4*)(g_attn + (size_t)row * 4);
    float ap[4] = {av.x, av.y, av.z, av.w};
    const float* tbp = g_tbias + (b*8 + head)*4;
    float tn[4] = {tbp[0], tbp[1], tbp[2], tbp[3]};

    float m = -1e30f;
    #pragma unroll
    for (int n = 0; n < 4; n++)
        #pragma unroll
        for (int p = 0; p < 4; p++) m = fmaxf(m, ap[p] + tn[n]);
    float pr[4][4]; float ssum = 0.0f;
    #pragma unroll
    for (int n = 0; n < 4; n++)
        #pragma unroll
        for (int p = 0; p < 4; p++){
            float e = expf(ap[p] + tn[n] - m);
            pr[n][p] = e; ssum += e;
        }
    float inv = 1.0f / ssum;
    float ent = 0.0f;
    #pragma unroll
    for (int n = 0; n < 4; n++)
        #pragma unroll
        for (int p = 0; p < 4; p++){
            float a = pr[n][p] * inv;
            pr[n][p] = a;
            ent -= a * logf(a + 1e-8f);
        }
    g_ent[row] = ent;

    float offs[8];
    {
        const float4* of = (const float4*)(g_off + (size_t)row * 8);
        float4 o0 = of[0], o1 = of[1];
        offs[0]=o0.x; offs[1]=o0.y; offs[2]=o0.z; offs[3]=o0.w;
        offs[4]=o1.x; offs[5]=o1.y; offs[6]=o1.z; offs[7]=o1.w;
    }
    float gx = -1.0f + x * (2.0f/95.0f);
    float gy = -1.0f + y * (2.0f/95.0f);
    float acc[16];
    #pragma unroll
    for (int k = 0; k < 16; k++) acc[k] = 0.0f;
    size_t vhbase = ((size_t)b*32 + head) * (size_t)(HW*8);

    #pragma unroll
    for (int p = 0; p < 4; p++){
        float sgx = fminf(fmaxf(gx + offs[2*p],   -1.0f), 1.0f);
        float sgy = fminf(fmaxf(gy + offs[2*p+1], -1.0f), 1.0f);
        float ix = (sgx + 1.0f) * 0.5f * 95.0f;
        float iy = (sgy + 1.0f) * 0.5f * 95.0f;
        float x0f = floorf(ix), y0f = floorf(iy);
        float wx = ix - x0f, wy = iy - y0f;
        int x0 = min(max((int)x0f, 0), 95), x1 = min(max((int)x0f + 1, 0), 95);
        int y0 = min(max((int)y0f, 0), 95), y1 = min(max((int)y0f + 1, 0), 95);
        int ti[4] = {(y0*WN+x0)*8, (y0*WN+x1)*8, (y1*WN+x0)*8, (y1*WN+x1)*8};
        float tw4[4] = {(1.f-wx)*(1.f-wy), wx*(1.f-wy), (1.f-wx)*wy, wx*wy};
        #pragma unroll
        for (int n = 0; n < 4; n++){
            const __half2* vbh = g_vh + vhbase + (size_t)n * (8*HW*8);
            float an = pr[n][p];
            #pragma unroll
            for (int t = 0; t < 4; t++){
                float cw = an * tw4[t];
                const uint4* pp = (const uint4*)(vbh + ti[t]);
                uint4 A = pp[0], Bv = pp[1];
                float2 f;
                f = __half22float2(*(__half2*)&A.x);  acc[0]  += cw*f.x; acc[1]  += cw*f.y;
                f = __half22float2(*(__half2*)&A.y);  acc[2]  += cw*f.x; acc[3]  += cw*f.y;
                f = __half22float2(*(__half2*)&A.z);  acc[4]  += cw*f.x; acc[5]  += cw*f.y;
                f = __half22float2(*(__half2*)&A.w);  acc[6]  += cw*f.x; acc[7]  += cw*f.y;
                f = __half22float2(*(__half2*)&Bv.x); acc[8]  += cw*f.x; acc[9]  += cw*f.y;
                f = __half22float2(*(__half2*)&Bv.y); acc[10] += cw*f.x; acc[11] += cw*f.y;
                f = __half22float2(*(__half2*)&Bv.z); acc[12] += cw*f.x; acc[13] += cw*f.y;
                f = __half22float2(*(__half2*)&Bv.w); acc[14] += cw*f.x; acc[15] += cw*f.y;
            }
        }
    }
    size_t ob = ((size_t)b*128 + head*16) * (size_t)HW + px;
    #pragma unroll
    for (int hd = 0; hd < 16; hd++)
        g_agg[ob + (size_t)hd * HW] = acc[hd];
}

// ---------------- entropy reduce over heads -> confidence ----------------
__global__ void __launch_bounds__(256) entconf_k(float* __restrict__ outp)
{
    int i = blockIdx.x * 256 + threadIdx.x;   // B*HW = 18432
    int b = i / HW, px = i - b * HW;
    float s = 0.0f;
    #pragma unroll
    for (int hh = 0; hh < 8; hh++) s += g_ent[((size_t)b*8 + hh)*HW + px];
    s *= 0.125f;
    float c = 1.0f - fminf(fmaxf(s * (1.0f/(2.772588722239781f + 1e-8f)), 0.0f), 1.0f);
    outp[2359296 + i] = c;
    outp[2359296 + 18432 + i] = s;
}

// ---------------- launch (multi-stream fork/join, capture-safe) ----------------
extern "C" void kernel_launch(void* const* d_in, const int* in_sizes, int n_in,
                              void* d_out, int out_size)
{
    const float* query    = (const float*)d_in[0];
    const float* values   = (const float*)d_in[1];
    const float* rel_time = (const float*)d_in[2];
    const float* time_enc = (const float*)d_in[3];
    const float* qw  = (const float*)d_in[4];
    const float* qb  = (const float*)d_in[5];
    const float* vw  = (const float*)d_in[6];
    const float* vb  = (const float*)d_in[7];
    const float* dww = (const float*)d_in[8];
    const float* dwb = (const float*)d_in[9];
    const float* pww = (const float*)d_in[10];
    const float* pwb = (const float*)d_in[11];
    const float* wih = (const float*)d_in[12];
    const float* whh = (const float*)d_in[13];
    const float* bih = (const float*)d_in[14];
    const float* bhh = (const float*)d_in[15];
    const float* offw = (const float*)d_in[16];
    const float* offb = (const float*)d_in[17];
    const float* aw  = (const float*)d_in[18];
    const float* ab  = (const float*)d_in[19];
    const float* tw  = (const float*)d_in[20];
    const float* tb  = (const float*)d_in[21];
    const float* o1w = (const float*)d_in[22];
    const float* o1b = (const float*)d_in[23];
    const float* o2w = (const float*)d_in[24];
    const float* o2b = (const float*)d_in[25];
    const float* gate = (const float*)d_in[26];
    float* outp = (float*)d_out;

    float *qperm, *vnear, *dwtmp, *net, *agg, *tmp2;
    __half2* vh;
    cudaGetSymbolAddress((void**)&qperm, g_qperm);
    cudaGetSymbolAddress((void**)&vnear, g_vnear);
    cudaGetSymbolAddress((void**)&vh,    g_vh);
    cudaGetSymbolAddress((void**)&dwtmp, g_dwtmp);
    cudaGetSymbolAddress((void**)&net,   g_net);
    cudaGetSymbolAddress((void**)&agg,   g_agg);
    cudaGetSymbolAddress((void**)&tmp2,  g_tmp2);

    cudaFuncSetAttribute((const void*)conv1x1_k<1>, cudaFuncAttributeMaxDynamicSharedMemorySize, CONV_SMEM_BYTES);
    cudaFuncSetAttribute((const void*)conv1x1_k<2>, cudaFuncAttributeMaxDynamicSharedMemorySize, CONV_SMEM_BYTES);
    cudaFuncSetAttribute((const void*)conv1x1_k<3>, cudaFuncAttributeMaxDynamicSharedMemorySize, CONV_SMEM_BYTES);
    cudaFuncSetAttribute((const void*)conv1x1_k<4>, cudaFuncAttributeMaxDynamicSharedMemorySize, CONV_SMEM_BYTES);
    cudaFuncSetAttribute((const void*)convh_k,      cudaFuncAttributeMaxDynamicSharedMemorySize, CONVH_SMEM_BYTES);

    // side streams + fork/join events (host-side objects; allocation-free on device)
    cudaStream_t sA, sB, sC;
    cudaStreamCreateWithFlags(&sA, cudaStreamNonBlocking);
    cudaStreamCreateWithFlags(&sB, cudaStreamNonBlocking);
    cudaStreamCreateWithFlags(&sC, cudaStreamNonBlocking);
    cudaEvent_t eRoot, eA, eB, eC;
    cudaEventCreateWithFlags(&eRoot, cudaEventDisableTiming);
    cudaEventCreateWithFlags(&eA,    cudaEventDisableTiming);
    cudaEventCreateWithFlags(&eB,    cudaEventDisableTiming);
    cudaEventCreateWithFlags(&eC,    cudaEventDisableTiming);

    // root: prep (g_nearest, g_tbias) on the capture-origin (default) stream
    prep_k<<<1, 64>>>(rel_time, time_enc, tw, tb);
    cudaEventRecord(eRoot, 0);

    // branch A (sA): q-conv + vnear-conv  -> qperm, vnear   (needed by corr)
    cudaStreamWaitEvent(sA, eRoot, 0);
    conv1x1_k<3><<<dim3(144, NB), 256, CONV_SMEM_BYTES, sA>>>(query,  qw, qb, qperm, nullptr);
    conv1x1_k<4><<<dim3(144, NB), 256, CONV_SMEM_BYTES, sA>>>(values, vw, vb, vnear, nullptr);
    cudaEventRecord(eA, sA);

    // branch B (sB): dwconv -> pw-conv -> net   (needed by gru)
    cudaStreamWaitEvent(sB, eRoot, 0);
    dwconv_k    <<<dim3(6, NB*CC), dim3(96, 4), 0, sB>>>(query, dww, dwb, dwtmp);
    conv1x1_k<3><<<dim3(144, NB), 256, CONV_SMEM_BYTES, sB>>>(dwtmp, pww, pwb, net, nullptr);
    cudaEventRecord(eB, sB);

    // branch C (sC): convh -> vh   (needed only by final)
    cudaStreamWaitEvent(sC, eRoot, 0);
    convh_k<<<dim3(72, NB*NF), 256, CONVH_SMEM_BYTES, sC>>>(values, vw, vb, vh);
    cudaEventRecord(eC, sC);

    // main stream: corr after A; gru after B; final after C
    cudaStreamWaitEvent(0, eA, 0);
    corr_k<<<576, 256>>>();
    cudaStreamWaitEvent(0, eB, 0);
    for (int it = 0; it < 3; it++)
        gru_k<<<1152, 128>>>(wih, whh, bih, bhh, offw, offb, aw, ab);
    cudaStreamWaitEvent(0, eC, 0);
    final_k<<<576, 256>>>();
    conv1x1_k<1><<<dim3(144, NB), 256, CONV_SMEM_BYTES>>>(agg,  o1w, o1b, tmp2, nullptr);
    conv1x1_k<2><<<dim3(144, NB), 256, CONV_SMEM_BYTES>>>(tmp2, o2w, o2b, outp, gate);
    entconf_k<<<72, 256>>>(outp);

    cudaEventDestroy(eRoot); cudaEventDestroy(eA);
    cudaEventDestroy(eB);    cudaEventDestroy(eC);
    cudaStreamDestroy(sA); cudaStreamDestroy(sB); cudaStreamDestroy(sC);
}